// round 16
// baseline (speedup 1.0000x reference)
#include <cuda_runtime.h>
#include <cuda_bf16.h>
#include <stdint.h>
#include <math.h>

#define B_ 4
#define L_ 4096
#define DM_ 1024
#define H_ 16
#define DH_ 64
#define K_ 8
#define C_ 512
#define BL_ (B_*L_)
#define HD_ (H_*DH_)

__device__ int   g_bid_q[B_*H_*L_];
__device__ int   g_bid_k[B_*H_*L_];
__device__ int   g_srt_q[B_*H_*L_];
__device__ int   g_srt_k[B_*H_*L_];
__device__ float g_mix_q[H_*DH_*K_];
__device__ float g_mix_k[H_*DH_*K_];
__device__ float g_psum_q[B_*H_*K_];
__device__ float g_fsum_q[B_*H_*K_];
__device__ float g_psum_k[B_*H_*K_];
__device__ float g_fsum_k[B_*H_*K_];

__device__ __nv_bfloat16 g_xhi[BL_*DM_];
__device__ __nv_bfloat16 g_xlo[BL_*DM_];
__device__ __nv_bfloat16 g_qhi[BL_*HD_];
__device__ __nv_bfloat16 g_qlo[BL_*HD_];
__device__ __nv_bfloat16 g_khi[BL_*HD_];
__device__ __nv_bfloat16 g_klo[BL_*HD_];
__device__ __nv_bfloat16 g_vhi[BL_*HD_];
__device__ __nv_bfloat16 g_vlo[BL_*HD_];
__device__ __nv_bfloat16 g_ohi[BL_*HD_];
__device__ __nv_bfloat16 g_olo[BL_*HD_];
__device__ __nv_bfloat16 g_wThi[3*DM_*HD_];
__device__ __nv_bfloat16 g_wTlo[3*DM_*HD_];
__device__ __nv_bfloat16 g_woThi[DM_*HD_];
__device__ __nv_bfloat16 g_woTlo[DM_*HD_];
__device__ float g_wsc[DM_*256];
__device__ float g_bsc[256];
__device__ float g_scores[(size_t)BL_*256];

__device__ __forceinline__ uint32_t smem_u32(const void* p) {
    uint32_t a;
    asm("{ .reg .u64 t; cvta.to.shared.u64 t, %1; cvt.u32.u64 %0, t; }" : "=r"(a) : "l"(p));
    return a;
}
__device__ __forceinline__ uint32_t pack_bf16(float a, float b) {
    __nv_bfloat162 t;
    t.x = __float2bfloat16(a); t.y = __float2bfloat16(b);
    return *(uint32_t*)&t;
}
__device__ __forceinline__ float bf_res(float a) {
    return a - __bfloat162float(__float2bfloat16(a));
}
#define MMA16816(d, a0,a1,a2,a3, b0,b1) \
    asm volatile("mma.sync.aligned.m16n8k16.row.col.f32.bf16.bf16.f32 " \
        "{%0,%1,%2,%3}, {%4,%5,%6,%7}, {%8,%9}, {%0,%1,%2,%3};" \
        : "+f"((d)[0]), "+f"((d)[1]), "+f"((d)[2]), "+f"((d)[3]) \
        : "r"(a0), "r"(a1), "r"(a2), "r"(a3), "r"(b0), "r"(b1))
#define LDSM4(R0,R1,R2,R3,ADDR) \
    asm volatile("ldmatrix.sync.aligned.m8n8.x4.shared.b16 {%0,%1,%2,%3}, [%4];" \
        : "=r"(R0), "=r"(R1), "=r"(R2), "=r"(R3) : "r"(ADDR))
#define LDSM4T(R0,R1,R2,R3,ADDR) \
    asm volatile("ldmatrix.sync.aligned.m8n8.x4.trans.shared.b16 {%0,%1,%2,%3}, [%4];" \
        : "=r"(R0), "=r"(R1), "=r"(R2), "=r"(R3) : "r"(ADDR))
#define CPA16(DST, SRC) \
    asm volatile("cp.async.cg.shared.global [%0], [%1], 16;" :: "r"(DST), "l"(SRC))

/* ===================== prep ===================== */
__global__ void prep_kernel(const float* __restrict__ wsh,
                            const float* __restrict__ wqs,
                            const float* __restrict__ wks) {
    int i = blockIdx.x * blockDim.x + threadIdx.x;
    if (i < H_*DH_*K_) {
        float s = wsh[i];
        g_mix_q[i] = 0.9f * s + 0.1f * wqs[i];
        g_mix_k[i] = 0.9f * s + 0.1f * wks[i];
    }
    if (i < B_*H_*K_) {
        g_psum_q[i] = 0.f; g_fsum_q[i] = 0.f;
        g_psum_k[i] = 0.f; g_fsum_k[i] = 0.f;
    }
}

/* pre-contract score weights */
__global__ void wsc_kernel(const float* __restrict__ wq, const float* __restrict__ wk,
                           const float* __restrict__ bq, const float* __restrict__ bk) {
    int i = blockIdx.x * 256 + threadIdx.x;
    int dm = i >> 8, col = i & 255;
    int isK = col >> 7, hc = col & 127;
    int h = hc >> 3, k = hc & 7;
    const float* w   = isK ? wk : wq;
    const float* mix = isK ? g_mix_k : g_mix_q;
    float s = 0.f;
#pragma unroll 8
    for (int d = 0; d < 64; d++)
        s += w[dm*1024 + h*64 + d] * mix[h*512 + d*8 + k];
    g_wsc[dm*256 + col] = s;
    if (i < 256) {
        const float* bb = isK ? bk : bq;
        float t = 0.f;
        for (int d = 0; d < 64; d++) t += bb[h*64 + d] * mix[h*512 + d*8 + k];
        g_bsc[col] = t;
    }
}

/* ===================== fp32 -> hi/lo bf16 split ===================== */
__global__ void split_kernel(const float* __restrict__ in,
                             __nv_bfloat16* __restrict__ hi,
                             __nv_bfloat16* __restrict__ lo, int n4) {
    int i = blockIdx.x * blockDim.x + threadIdx.x;
    if (i >= n4) return;
    float4 v = ((const float4*)in)[i];
    ((uint32_t*)hi)[i*2]   = pack_bf16(v.x, v.y);
    ((uint32_t*)hi)[i*2+1] = pack_bf16(v.z, v.w);
    ((uint32_t*)lo)[i*2]   = pack_bf16(bf_res(v.x), bf_res(v.y));
    ((uint32_t*)lo)[i*2+1] = pack_bf16(bf_res(v.z), bf_res(v.w));
}

/* transpose [1024,1024] fp32 -> [N,K] hi/lo bf16 */
__global__ void transpose_split_kernel(const float* __restrict__ in,
                                       __nv_bfloat16* __restrict__ hi,
                                       __nv_bfloat16* __restrict__ lo) {
    __shared__ float t[32][33];
    int bx = blockIdx.x * 32, by = blockIdx.y * 32;
    int x = threadIdx.x, y = threadIdx.y;
#pragma unroll
    for (int i = 0; i < 32; i += 8)
        t[y + i][x] = in[(size_t)(by + y + i) * 1024 + bx + x];
    __syncthreads();
#pragma unroll
    for (int i = 0; i < 32; i += 8) {
        float v = t[x][y + i];
        size_t oidx = (size_t)(bx + y + i) * 1024 + by + x;
        hi[oidx] = __float2bfloat16(v);
        lo[oidx] = __float2bfloat16(bf_res(v));
    }
}

/* ============ HMMA split-bf16 GEMM (R13: BK=64, 48 stages) ============ */
#define GBK 64
#define GSTR 72
#define STAGE_ELEMS (2*128*GSTR)
#define SMEM_MMA (3*STAGE_ELEMS*2)

__global__ __launch_bounds__(256, 2) void gemm_mma_kernel(
    const __nv_bfloat16* __restrict__ Ahi, const __nv_bfloat16* __restrict__ Alo,
    const __nv_bfloat16* __restrict__ WhiB, const __nv_bfloat16* __restrict__ WloB,
    const float* __restrict__ bias0, const float* __restrict__ bias1,
    const float* __restrict__ bias2,
    float* __restrict__ Cf, int obf, int moff,
    __nv_bfloat16* __restrict__ Qh, __nv_bfloat16* __restrict__ Ql,
    __nv_bfloat16* __restrict__ Kh, __nv_bfloat16* __restrict__ Kl,
    __nv_bfloat16* __restrict__ Vh, __nv_bfloat16* __restrict__ Vl) {
    extern __shared__ __align__(16) __nv_bfloat16 sm[];
    int tid = threadIdx.x, lane = tid & 31, w = tid >> 5;
    int wm = w & 1, wn = w >> 1;
    int Nbase = blockIdx.x * 128, Mbase = (blockIdx.y + moff) * 128;
    int z = blockIdx.z;
    const __nv_bfloat16* Whi = WhiB + (size_t)z * DM_ * HD_;
    const __nv_bfloat16* Wlo = WloB + (size_t)z * DM_ * HD_;
    const float* bias = (z == 0) ? bias0 : (z == 1) ? bias1 : bias2;

    float acc[4][4][4];
#pragma unroll
    for (int m = 0; m < 4; m++)
#pragma unroll
        for (int n = 0; n < 4; n++)
#pragma unroll
            for (int e = 0; e < 4; e++) acc[m][n][e] = 0.f;

    int ldrow = tid >> 3, ldch = tid & 7;
    uint32_t smbase = smem_u32(sm);

    int a_off = ((wm * 64 + (lane & 15)) * GSTR + ((lane >> 4) << 3)) * 2;
    int b_off = ((wn * 32 + (lane & 7) + (((lane >> 4) & 1) << 3)) * GSTR
                 + (((lane >> 3) & 1) << 3)) * 2;

    auto load_stage = [&](int s) {
        int st = s % 3;
        int kb = s * GBK;
        int blk = kb >> 10;
        const __nv_bfloat16* As = (blk == 1) ? Alo : Ahi;
        const __nv_bfloat16* Ws = (blk == 2) ? Wlo : Whi;
        int kk = kb & (DM_ - 1);
        __nv_bfloat16* sA = sm + st * STAGE_ELEMS;
        __nv_bfloat16* sB = sA + 128 * GSTR;
#pragma unroll
        for (int i = 0; i < 4; i++) {
            int row = ldrow + i * 32;
            const __nv_bfloat16* srcA = As + (size_t)(Mbase + row) * DM_ + kk + ldch * 8;
            CPA16(smem_u32(sA + row * GSTR + ldch * 8), srcA);
            const __nv_bfloat16* srcB = Ws + (size_t)(Nbase + row) * DM_ + kk + ldch * 8;
            CPA16(smem_u32(sB + row * GSTR + ldch * 8), srcB);
        }
    };

    load_stage(0); asm volatile("cp.async.commit_group;" ::: "memory");
    load_stage(1); asm volatile("cp.async.commit_group;" ::: "memory");

    for (int s = 0; s < 48; s++) {
        int st = s % 3;
        if (s < 47) asm volatile("cp.async.wait_group 1;" ::: "memory");
        else        asm volatile("cp.async.wait_group 0;" ::: "memory");
        __syncthreads();
        uint32_t uA = smbase + st * STAGE_ELEMS * 2;
        uint32_t uB = uA + 128 * GSTR * 2;
#pragma unroll
        for (int kt = 0; kt < 4; kt++) {
            int cb = kt * 16 * 2;
            uint32_t a[4][4];
#pragma unroll
            for (int mt = 0; mt < 4; mt++)
                LDSM4(a[mt][0], a[mt][1], a[mt][2], a[mt][3],
                      uA + a_off + mt * 16 * GSTR * 2 + cb);
            uint32_t b[4][2];
#pragma unroll
            for (int p2 = 0; p2 < 2; p2++)
                LDSM4(b[p2*2][0], b[p2*2][1], b[p2*2+1][0], b[p2*2+1][1],
                      uB + b_off + p2 * 16 * GSTR * 2 + cb);
#pragma unroll
            for (int mt = 0; mt < 4; mt++)
#pragma unroll
                for (int nt = 0; nt < 4; nt++)
                    MMA16816(acc[mt][nt], a[mt][0], a[mt][1], a[mt][2], a[mt][3],
                             b[nt][0], b[nt][1]);
        }
        if (s + 2 < 48) {
            load_stage(s + 2);
            asm volatile("cp.async.commit_group;" ::: "memory");
        }
    }

    int gr0 = Mbase + wm * 64 + (lane >> 2);
    int gc0 = Nbase + wn * 32 + (lane & 3) * 2;
    if (obf) {
        __nv_bfloat16* Hi = (z == 0) ? Qh : (z == 1) ? Kh : Vh;
        __nv_bfloat16* Lo = (z == 0) ? Ql : (z == 1) ? Kl : Vl;
        float scale = (z == 0) ? 0.125f : 1.f;
#pragma unroll
        for (int mt = 0; mt < 4; mt++) {
#pragma unroll
            for (int nt = 0; nt < 4; nt++) {
                int r = gr0 + mt * 16;
                int cc = gc0 + nt * 8;
                float b0 = bias[cc], b1 = bias[cc + 1];
                float v0 = (acc[mt][nt][0] + b0) * scale;
                float v1 = (acc[mt][nt][1] + b1) * scale;
                float v2 = (acc[mt][nt][2] + b0) * scale;
                float v3 = (acc[mt][nt][3] + b1) * scale;
                *(uint32_t*)(Hi + (size_t)r * 1024 + cc) = pack_bf16(v0, v1);
                *(uint32_t*)(Lo + (size_t)r * 1024 + cc) = pack_bf16(bf_res(v0), bf_res(v1));
                *(uint32_t*)(Hi + (size_t)(r + 8) * 1024 + cc) = pack_bf16(v2, v3);
                *(uint32_t*)(Lo + (size_t)(r + 8) * 1024 + cc) = pack_bf16(bf_res(v2), bf_res(v3));
            }
        }
    } else {
#pragma unroll
        for (int mt = 0; mt < 4; mt++) {
#pragma unroll
            for (int nt = 0; nt < 4; nt++) {
                int r = gr0 + mt * 16;
                int cc = gc0 + nt * 8;
                float b0 = bias[cc], b1 = bias[cc + 1];
                float2 v0 = make_float2(acc[mt][nt][0] + b0, acc[mt][nt][1] + b1);
                float2 v1 = make_float2(acc[mt][nt][2] + b0, acc[mt][nt][3] + b1);
                *(float2*)(Cf + (size_t)r * 1024 + cc) = v0;
                *(float2*)(Cf + (size_t)(r + 8) * 1024 + cc) = v1;
            }
        }
    }
}

/* ===================== fp32 GEMM (score path) ===================== */
#define BM 128
#define BN 128
#define BK 16
__global__ __launch_bounds__(256) void gemm_bias_kernel(
    const float* __restrict__ A, const float* __restrict__ Bm,
    const float* __restrict__ bias, float* __restrict__ C,
    int M, int N, int Kd) {
    __shared__ float As[BK][BM + 4];
    __shared__ float Bs[BK][BN];
    int tid = threadIdx.x;
    int brow = blockIdx.y * BM;
    int bcol = blockIdx.x * BN;
    int tx = tid & 15, ty = tid >> 4;
    float acc[8][8];
#pragma unroll
    for (int i = 0; i < 8; i++)
#pragma unroll
        for (int j = 0; j < 8; j++) acc[i][j] = 0.f;

    for (int k0 = 0; k0 < Kd; k0 += BK) {
#pragma unroll
        for (int i = 0; i < 2; i++) {
            int lin = tid + i * 256;
            int r = lin >> 2, kc = (lin & 3) * 4;
            float4 av = *(const float4*)(A + (size_t)(brow + r) * Kd + k0 + kc);
            As[kc + 0][r] = av.x; As[kc + 1][r] = av.y;
            As[kc + 2][r] = av.z; As[kc + 3][r] = av.w;
        }
#pragma unroll
        for (int i = 0; i < 2; i++) {
            int lin = tid + i * 256;
            int r = lin >> 5, c = (lin & 31) * 4;
            *(float4*)&Bs[r][c] = *(const float4*)(Bm + (size_t)(k0 + r) * N + bcol + c);
        }
        __syncthreads();
#pragma unroll
        for (int kk = 0; kk < BK; kk++) {
            float4 a0 = *(const float4*)&As[kk][ty * 8];
            float4 a1 = *(const float4*)&As[kk][ty * 8 + 4];
            float4 b0 = *(const float4*)&Bs[kk][tx * 8];
            float4 b1 = *(const float4*)&Bs[kk][tx * 8 + 4];
            float a[8] = {a0.x,a0.y,a0.z,a0.w,a1.x,a1.y,a1.z,a1.w};
            float bb[8] = {b0.x,b0.y,b0.z,b0.w,b1.x,b1.y,b1.z,b1.w};
#pragma unroll
            for (int i = 0; i < 8; i++)
#pragma unroll
                for (int j = 0; j < 8; j++) acc[i][j] += a[i] * bb[j];
        }
        __syncthreads();
    }
#pragma unroll
    for (int i = 0; i < 8; i++) {
        int r = brow + ty * 8 + i;
#pragma unroll
        for (int j = 0; j < 8; j += 4) {
            int c = bcol + tx * 8 + j;
            float4 ov = make_float4(acc[i][j]   + bias[c],
                                    acc[i][j+1] + bias[c+1],
                                    acc[i][j+2] + bias[c+2],
                                    acc[i][j+3] + bias[c+3]);
            *(float4*)(C + (size_t)r * N + c) = ov;
        }
    }
}

/* ============ argmax + routing-loss accumulation ============ */
__global__ __launch_bounds__(256) void argmax_kernel(
    const float* __restrict__ sc, int off,
    int* __restrict__ bid, float* __restrict__ p_sum, float* __restrict__ f_sum) {
    __shared__ float red_p[16][K_];
    __shared__ float red_f[16][K_];
    int tid = threadIdx.x;
    if (tid < 128) { ((float*)red_p)[tid] = 0.f; ((float*)red_f)[tid] = 0.f; }
    __syncthreads();
    int i = blockIdx.x * 256 + tid;
    int h = i & 15, bl = i >> 4;
    int b = bl >> 12, l = bl & (L_ - 1);
    const float* s = sc + (size_t)bl * 256 + off + h * 8;
    float v[K_];
    float4 s0 = *(const float4*)s;
    float4 s1 = *(const float4*)(s + 4);
    v[0]=s0.x; v[1]=s0.y; v[2]=s0.z; v[3]=s0.w;
    v[4]=s1.x; v[5]=s1.y; v[6]=s1.z; v[7]=s1.w;
    int am = 0; float mx = v[0];
#pragma unroll
    for (int k = 1; k < K_; k++) if (v[k] > mx) { mx = v[k]; am = k; }
    bid[(b * H_ + h) * L_ + l] = am;
    float esum = 0.f, e[K_];
#pragma unroll
    for (int k = 0; k < K_; k++) { e[k] = __expf(v[k] - mx); esum += e[k]; }
    float inv = 1.f / esum;
#pragma unroll
    for (int k = 0; k < K_; k++) atomicAdd(&red_p[h][k], e[k] * inv);
    atomicAdd(&red_f[h][am], 1.f);
    __syncthreads();
    if (tid < 128) {
        int hh = tid >> 3, kk = tid & 7;
        atomicAdd(&p_sum[(b * H_ + hh) * K_ + kk], red_p[hh][kk]);
        atomicAdd(&f_sum[(b * H_ + hh) * K_ + kk], red_f[hh][kk]);
    }
}

/* ============ stable counting sort ============ */
__global__ __launch_bounds__(512) void sort_kernel(const int* __restrict__ bid,
                                                   int* __restrict__ srt) {
    __shared__ int cnt[K_][513];
    __shared__ int bstart[K_];
    int bh = blockIdx.x;
    const int* bb = bid + (size_t)bh * L_;
    int t = threadIdx.x;
    int myb[8], local[K_];
#pragma unroll
    for (int k = 0; k < K_; k++) local[k] = 0;
#pragma unroll
    for (int j = 0; j < 8; j++) { myb[j] = bb[t * 8 + j]; local[myb[j]]++; }
#pragma unroll
    for (int k = 0; k < K_; k++) cnt[k][t + 1] = local[k];
    if (t < K_) cnt[t][0] = 0;
    __syncthreads();
    if (t < K_) {
        int run = 0;
        for (int i = 1; i <= 512; i++) { run += cnt[t][i]; cnt[t][i] = run; }
    }
    __syncthreads();
    if (t == 0) {
        int a = 0;
        for (int k = 0; k < K_; k++) { bstart[k] = a; a += cnt[k][512]; }
    }
    __syncthreads();
    int off[K_];
#pragma unroll
    for (int k = 0; k < K_; k++) off[k] = bstart[k] + cnt[k][t];
    int* so = srt + (size_t)bh * L_;
#pragma unroll
    for (int j = 0; j < 8; j++) {
        int bkt = myb[j];
        so[off[bkt]++] = t * 8 + j;
    }
}

/* ============== FA2-style flash attention (proven R13 version) ======== */
#define AQHI 0
#define AQLO 9216
#define AKHI 18432
#define AKLO 27648
#define AVHI 36864
#define AVLO 46080
#define AT_SMEM 55296

__global__ __launch_bounds__(128, 3) void attn_mma_kernel(int boff) {
    extern __shared__ __align__(16) char sb[];
    uint32_t sbase = smem_u32(sb);

    int tid = threadIdx.x, lane = tid & 31, w = tid >> 5;
    int lr = lane >> 2, lq = lane & 3;
    int idx = blockIdx.x + boff;
    int qt    = idx & 7;
    int chunk = (idx >> 3) & 7;
    int h     = (idx >> 6) & 15;
    int b     = idx >> 10;
    int qbase = (b * H_ + h) * L_ + chunk * C_ + qt * 64;
    int kbase = (b * H_ + h) * L_ + chunk * C_;

    int a_off = ((w * 16 + (lane & 15)) * 72 + ((lane >> 4) << 3)) * 2;
    int k_off = (((lane & 7) + (((lane >> 4) & 1) << 3)) * 72
                 + (((lane >> 3) & 1) << 3)) * 2;
    int v_off = (((lane & 7) + (((lane >> 3) & 1) << 3)) * 72
                 + (((lane >> 4) & 1) << 3)) * 2;

    {
        int r = tid >> 1, cc = (tid & 1) * 32;
        int qi = g_srt_q[qbase + r];
        size_t go = (size_t)(b * L_ + qi) * HD_ + h * DH_ + cc;
        int e = (r * 72 + cc) * 2;
#pragma unroll
        for (int j = 0; j < 4; j++) {
            *(uint4*)(sb + AQHI + e + j * 16) = ((const uint4*)(g_qhi + go))[j];
            *(uint4*)(sb + AQLO + e + j * 16) = ((const uint4*)(g_qlo + go))[j];
        }
    }
    __syncthreads();

    uint32_t qa[2][4][4];
#pragma unroll
    for (int kb = 0; kb < 4; kb++) {
        LDSM4(qa[0][kb][0], qa[0][kb][1], qa[0][kb][2], qa[0][kb][3],
              sbase + AQHI + a_off + kb * 32);
        LDSM4(qa[1][kb][0], qa[1][kb][1], qa[1][kb][2], qa[1][kb][3],
              sbase + AQLO + a_off + kb * 32);
    }

    int qi0 = g_srt_q[qbase + w * 16 + lr];
    int qi1 = g_srt_q[qbase + w * 16 + lr + 8];

    float acc_o[8][4];
#pragma unroll
    for (int nt = 0; nt < 8; nt++)
#pragma unroll
        for (int e = 0; e < 4; e++) acc_o[nt][e] = 0.f;
    float m0 = -1e30f, m1 = -1e30f, l0 = 0.f, l1 = 0.f;

    for (int t = 0; t < 8; t++) {
        __syncthreads();
        {
            int r = tid >> 1, cc = (tid & 1) * 32;
            int ki = g_srt_k[kbase + t * 64 + r];
            size_t go = (size_t)(b * L_ + ki) * HD_ + h * DH_ + cc;
            int e = (r * 72 + cc) * 2;
#pragma unroll
            for (int j = 0; j < 4; j++) {
                *(uint4*)(sb + AKHI + e + j * 16) = ((const uint4*)(g_khi + go))[j];
                *(uint4*)(sb + AKLO + e + j * 16) = ((const uint4*)(g_klo + go))[j];
                *(uint4*)(sb + AVHI + e + j * 16) = ((const uint4*)(g_vhi + go))[j];
                *(uint4*)(sb + AVLO + e + j * 16) = ((const uint4*)(g_vlo + go))[j];
            }
        }
        __syncthreads();

        float acc_s[8][4];
#pragma unroll
        for (int nt = 0; nt < 8; nt++)
#pragma unroll
            for (int e = 0; e < 4; e++) acc_s[nt][e] = 0.f;

#pragma unroll
        for (int kb = 0; kb < 4; kb++) {
#pragma unroll
            for (int p2 = 0; p2 < 4; p2++) {
                uint32_t bh0, bh1, bh2, bh3, bl0, bl1, bl2, bl3;
                LDSM4(bh0, bh1, bh2, bh3,
                      sbase + AKHI + k_off + p2 * 2304 + kb * 32);
                LDSM4(bl0, bl1, bl2, bl3,
                      sbase + AKLO + k_off + p2 * 2304 + kb * 32);
                MMA16816(acc_s[2*p2],   qa[0][kb][0], qa[0][kb][1], qa[0][kb][2], qa[0][kb][3], bh0, bh1);
                MMA16816(acc_s[2*p2+1], qa[0][kb][0], qa[0][kb][1], qa[0][kb][2], qa[0][kb][3], bh2, bh3);
                MMA16816(acc_s[2*p2],   qa[1][kb][0], qa[1][kb][1], qa[1][kb][2], qa[1][kb][3], bh0, bh1);
                MMA16816(acc_s[2*p2+1], qa[1][kb][0], qa[1][kb][1], qa[1][kb][2], qa[1][kb][3], bh2, bh3);
                MMA16816(acc_s[2*p2],   qa[0][kb][0], qa[0][kb][1], qa[0][kb][2], qa[0][kb][3], bl0, bl1);
                MMA16816(acc_s[2*p2+1], qa[0][kb][0], qa[0][kb][1], qa[0][kb][2], qa[0][kb][3], bl2, bl3);
            }
        }

        float mx0 = -1e30f, mx1 = -1e30f;
#pragma unroll
        for (int nt = 0; nt < 8; nt++) {
            mx0 = fmaxf(mx0, fmaxf(acc_s[nt][0], acc_s[nt][1]));
            mx1 = fmaxf(mx1, fmaxf(acc_s[nt][2], acc_s[nt][3]));
        }
        mx0 = fmaxf(mx0, __shfl_xor_sync(0xffffffff, mx0, 1));
        mx0 = fmaxf(mx0, __shfl_xor_sync(0xffffffff, mx0, 2));
        mx1 = fmaxf(mx1, __shfl_xor_sync(0xffffffff, mx1, 1));
        mx1 = fmaxf(mx1, __shfl_xor_sync(0xffffffff, mx1, 2));
        float mn0 = fmaxf(m0, mx0), mn1 = fmaxf(m1, mx1);
        float c0 = __expf(m0 - mn0), c1 = __expf(m1 - mn1);
        m0 = mn0; m1 = mn1;
        l0 *= c0; l1 *= c1;
#pragma unroll
        for (int nt = 0; nt < 8; nt++) {
            acc_o[nt][0] *= c0; acc_o[nt][1] *= c0;
            acc_o[nt][2] *= c1; acc_o[nt][3] *= c1;
        }

        float s0 = 0.f, s1 = 0.f;
#pragma unroll
        for (int nt = 0; nt < 8; nt++) {
            acc_s[nt][0] = __expf(acc_s[nt][0] - mn0);
            acc_s[nt][1] = __expf(acc_s[nt][1] - mn0);
            acc_s[nt][2] = __expf(acc_s[nt][2] - mn1);
            acc_s[nt][3] = __expf(acc_s[nt][3] - mn1);
            s0 += acc_s[nt][0] + acc_s[nt][1];
            s1 += acc_s[nt][2] + acc_s[nt][3];
        }
        s0 += __shfl_xor_sync(0xffffffff, s0, 1);
        s0 += __shfl_xor_sync(0xffffffff, s0, 2);
        s1 += __shfl_xor_sync(0xffffffff, s1, 1);
        s1 += __shfl_xor_sync(0xffffffff, s1, 2);
        l0 += s0; l1 += s1;

#pragma unroll
        for (int kb = 0; kb < 4; kb++) {
            uint32_t ph0 = pack_bf16(acc_s[2*kb][0],   acc_s[2*kb][1]);
            uint32_t ph1 = pack_bf16(acc_s[2*kb][2],   acc_s[2*kb][3]);
            uint32_t ph2 = pack_bf16(acc_s[2*kb+1][0], acc_s[2*kb+1][1]);
            uint32_t ph3 = pack_bf16(acc_s[2*kb+1][2], acc_s[2*kb+1][3]);
            uint32_t pl0 = pack_bf16(bf_res(acc_s[2*kb][0]),   bf_res(acc_s[2*kb][1]));
            uint32_t pl1 = pack_bf16(bf_res(acc_s[2*kb][2]),   bf_res(acc_s[2*kb][3]));
            uint32_t pl2 = pack_bf16(bf_res(acc_s[2*kb+1][0]), bf_res(acc_s[2*kb+1][1]));
            uint32_t pl3 = pack_bf16(bf_res(acc_s[2*kb+1][2]), bf_res(acc_s[2*kb+1][3]));
#pragma unroll
            for (int p2 = 0; p2 < 4; p2++) {
                uint32_t vh0, vh1, vh2, vh3, vl0, vl1, vl2, vl3;
                LDSM4T(vh0, vh1, vh2, vh3,
                       sbase + AVHI + v_off + kb * 2304 + p2 * 32);
                LDSM4T(vl0, vl1, vl2, vl3,
                       sbase + AVLO + v_off + kb * 2304 + p2 * 32);
                MMA16816(acc_o[2*p2],   ph0, ph1, ph2, ph3, vh0, vh1);
                MMA16816(acc_o[2*p2+1], ph0, ph1, ph2, ph3, vh2, vh3);
                MMA16816(acc_o[2*p2],   pl0, pl1, pl2, pl3, vh0, vh1);
                MMA16816(acc_o[2*p2+1], pl0, pl1, pl2, pl3, vh2, vh3);
                MMA16816(acc_o[2*p2],   ph0, ph1, ph2, ph3, vl0, vl1);
                MMA16816(acc_o[2*p2+1], ph0, ph1, ph2, ph3, vl2, vl3);
            }
        }
    }

    float inv0 = 1.f / l0, inv1 = 1.f / l1;
    size_t ro0 = (size_t)(b * L_ + qi0) * HD_ + h * DH_;
    size_t ro1 = (size_t)(b * L_ + qi1) * HD_ + h * DH_;
#pragma unroll
    for (int nt = 0; nt < 8; nt++) {
        int cc = nt * 8 + lq * 2;
        float a0 = acc_o[nt][0] * inv0, a1 = acc_o[nt][1] * inv0;
        float b0 = acc_o[nt][2] * inv1, b1 = acc_o[nt][3] * inv1;
        *(uint32_t*)(g_ohi + ro0 + cc) = pack_bf16(a0, a1);
        *(uint32_t*)(g_olo + ro0 + cc) = pack_bf16(bf_res(a0), bf_res(a1));
        *(uint32_t*)(g_ohi + ro1 + cc) = pack_bf16(b0, b1);
        *(uint32_t*)(g_olo + ro1 + cc) = pack_bf16(bf_res(b0), bf_res(b1));
    }
}

/* ===================== loss finalize ===================== */
__global__ void loss_kernel(float* __restrict__ out, int out_size) {
    if (out_size <= BL_ * DM_) return;
    float lq = 0.f, lk = 0.f;
    const float invL = 1.f / (float)L_;
    for (int i = 0; i < B_ * H_; i++) {
        float aq = 0.f, ak = 0.f;
        for (int k = 0; k < K_; k++) {
            aq += (g_fsum_q[i*K_+k] * invL) * (g_psum_q[i*K_+k] * invL);
            ak += (g_fsum_k[i*K_+k] * invL) * (g_psum_k[i*K_+k] * invL);
        }
        lq += aq; lk += ak;
    }
    lq = (float)K_ * lq / (float)(B_ * H_);
    lk = (float)K_ * lk / (float)(B_ * H_);
    out[BL_ * DM_] = 0.5f * (lq + lk);
}

/* ============ side streams / events (static init) ============ */
static cudaStream_t g_s2 = 0, g_s3 = 0;
static cudaEvent_t g_ev0 = 0, g_ev1 = 0, g_ev2 = 0, g_ev3 = 0, g_ev4 = 0;
namespace {
struct InitOnce {
    InitOnce() {
        cudaFree(0);
        cudaStreamCreateWithFlags(&g_s2, cudaStreamNonBlocking);
        cudaStreamCreateWithFlags(&g_s3, cudaStreamNonBlocking);
        cudaEventCreateWithFlags(&g_ev0, cudaEventDisableTiming);
        cudaEventCreateWithFlags(&g_ev1, cudaEventDisableTiming);
        cudaEventCreateWithFlags(&g_ev2, cudaEventDisableTiming);
        cudaEventCreateWithFlags(&g_ev3, cudaEventDisableTiming);
        cudaEventCreateWithFlags(&g_ev4, cudaEventDisableTiming);
    }
};
static InitOnce g_init_once;
}

/* ===================== launch ===================== */
extern "C" void kernel_launch(void* const* d_in, const int* in_sizes, int n_in,
                              void* d_out, int out_size) {
    const float* x   = (const float*)d_in[0];
    const float* wq  = (const float*)d_in[1];
    const float* bq  = (const float*)d_in[2];
    const float* wk  = (const float*)d_in[3];
    const float* bk  = (const float*)d_in[4];
    const float* wv  = (const float*)d_in[5];
    const float* bv  = (const float*)d_in[6];
    const float* wsh = (const float*)d_in[7];
    const float* wqs = (const float*)d_in[8];
    const float* wks = (const float*)d_in[9];
    const float* wo  = (const float*)d_in[10];
    const float* bo  = (const float*)d_in[11];
    float* out = (float*)d_out;

    void* p;
    cudaGetSymbolAddress(&p, g_bid_q); int* bidq = (int*)p;
    cudaGetSymbolAddress(&p, g_bid_k); int* bidk = (int*)p;
    cudaGetSymbolAddress(&p, g_srt_q); int* srtq = (int*)p;
    cudaGetSymbolAddress(&p, g_srt_k); int* srtk = (int*)p;
    cudaGetSymbolAddress(&p, g_psum_q); float* psq = (float*)p;
    cudaGetSymbolAddress(&p, g_fsum_q); float* fsq = (float*)p;
    cudaGetSymbolAddress(&p, g_psum_k); float* psk = (float*)p;
    cudaGetSymbolAddress(&p, g_fsum_k); float* fsk = (float*)p;
    cudaGetSymbolAddress(&p, g_xhi); __nv_bfloat16* xhi = (__nv_bfloat16*)p;
    cudaGetSymbolAddress(&p, g_xlo); __nv_bfloat16* xlo = (__nv_bfloat16*)p;
    cudaGetSymbolAddress(&p, g_qhi); __nv_bfloat16* qhi = (__nv_bfloat16*)p;
    cudaGetSymbolAddress(&p, g_qlo); __nv_bfloat16* qlo = (__nv_bfloat16*)p;
    cudaGetSymbolAddress(&p, g_khi); __nv_bfloat16* khi = (__nv_bfloat16*)p;
    cudaGetSymbolAddress(&p, g_klo); __nv_bfloat16* klo = (__nv_bfloat16*)p;
    cudaGetSymbolAddress(&p, g_vhi); __nv_bfloat16* vhi = (__nv_bfloat16*)p;
    cudaGetSymbolAddress(&p, g_vlo); __nv_bfloat16* vlo = (__nv_bfloat16*)p;
    cudaGetSymbolAddress(&p, g_ohi); __nv_bfloat16* ohi = (__nv_bfloat16*)p;
    cudaGetSymbolAddress(&p, g_olo); __nv_bfloat16* olo = (__nv_bfloat16*)p;
    cudaGetSymbolAddress(&p, g_wThi); __nv_bfloat16* wThi = (__nv_bfloat16*)p;
    cudaGetSymbolAddress(&p, g_wTlo); __nv_bfloat16* wTlo = (__nv_bfloat16*)p;
    cudaGetSymbolAddress(&p, g_woThi); __nv_bfloat16* woThi = (__nv_bfloat16*)p;
    cudaGetSymbolAddress(&p, g_woTlo); __nv_bfloat16* woTlo = (__nv_bfloat16*)p;
    cudaGetSymbolAddress(&p, g_wsc); float* wsc = (float*)p;
    cudaGetSymbolAddress(&p, g_bsc); float* bsc = (float*)p;
    cudaGetSymbolAddress(&p, g_scores); float* scores = (float*)p;

    cudaFuncSetAttribute(gemm_mma_kernel,
                         cudaFuncAttributeMaxDynamicSharedMemorySize, SMEM_MMA);
    cudaFuncSetAttribute(attn_mma_kernel,
                         cudaFuncAttributeMaxDynamicSharedMemorySize, AT_SMEM);

    /* ---- fork: s2 = split(x); s3 = weight transposes; join into QKV GEMM */
    cudaEventRecord(g_ev0, 0);
    cudaStreamWaitEvent(g_s2, g_ev0, 0);
    cudaStreamWaitEvent(g_s3, g_ev0, 0);

    split_kernel<<<(BL_*DM_/4 + 255)/256, 256, 0, g_s2>>>(x, xhi, xlo, BL_*DM_/4);

    dim3 tg(32, 32), tb(32, 8);
    transpose_split_kernel<<<tg, tb, 0, g_s3>>>(wq, wThi,             wTlo);
    transpose_split_kernel<<<tg, tb, 0, g_s3>>>(wk, wThi + DM_*HD_,   wTlo + DM_*HD_);
    transpose_split_kernel<<<tg, tb, 0, g_s3>>>(wv, wThi + 2*DM_*HD_, wTlo + 2*DM_*HD_);
    transpose_split_kernel<<<tg, tb, 0, g_s3>>>(wo, woThi,            woTlo);
    cudaEventRecord(g_ev2, g_s3);

    cudaStreamWaitEvent(g_s2, g_ev2, 0);
    gemm_mma_kernel<<<dim3(8, 128, 3), 256, SMEM_MMA, g_s2>>>(
        xhi, xlo, wThi, wTlo, bq, bk, bv,
        nullptr, 1, 0, qhi, qlo, khi, klo, vhi, vlo);
    cudaEventRecord(g_ev1, g_s2);

    /* ---- main stream: score / argmax / sort path (overlapped) ---- */
    prep_kernel<<<32, 256>>>(wsh, wqs, wks);
    wsc_kernel<<<1024, 256>>>(wq, wk, bq, bk);
    gemm_bias_kernel<<<dim3(2, 128), 256>>>(x, wsc, bsc, scores, BL_, 256, DM_);
    argmax_kernel<<<1024, 256>>>(scores, 0,   bidq, psq, fsq);
    argmax_kernel<<<1024, 256>>>(scores, 128, bidk, psk, fsk);
    sort_kernel<<<B_*H_, 512>>>(bidq, srtq);
    sort_kernel<<<B_*H_, 512>>>(bidk, srtk);

    /* ---- join, then pipelined attention / output projection ---- */
    cudaStreamWaitEvent(0, g_ev1, 0);
    /* attention half 1: batches 0,1 (blocks [0,2048)) */
    attn_mma_kernel<<<2048, 128, AT_SMEM>>>(0);
    cudaEventRecord(g_ev3, 0);
    /* attention half 2: batches 2,3 — overlaps out-proj half 1 on s2 */
    attn_mma_kernel<<<2048, 128, AT_SMEM>>>(2048);

    cudaStreamWaitEvent(g_s2, g_ev3, 0);
    gemm_mma_kernel<<<dim3(8, 64, 1), 256, SMEM_MMA, g_s2>>>(
        ohi, olo, woThi, woTlo, bo, bo, bo,
        out, 0, 0, nullptr, nullptr, nullptr, nullptr, nullptr, nullptr);
    cudaEventRecord(g_ev4, g_s2);

    /* out-proj half 2: M rows [8192,16384) = batches 2,3 (main, after attn2) */
    gemm_mma_kernel<<<dim3(8, 64, 1), 256, SMEM_MMA>>>(
        ohi, olo, woThi, woTlo, bo, bo, bo,
        out, 0, 64, nullptr, nullptr, nullptr, nullptr, nullptr, nullptr);

    cudaStreamWaitEvent(0, g_ev4, 0);
    loss_kernel<<<1, 1>>>(out, out_size);
}

// round 17
// speedup vs baseline: 1.0130x; 1.0130x over previous
#include <cuda_runtime.h>
#include <cuda_bf16.h>
#include <stdint.h>
#include <math.h>

#define B_ 4
#define L_ 4096
#define DM_ 1024
#define H_ 16
#define DH_ 64
#define K_ 8
#define C_ 512
#define BL_ (B_*L_)
#define HD_ (H_*DH_)

__device__ int   g_bid_q[B_*H_*L_];
__device__ int   g_bid_k[B_*H_*L_];
__device__ int   g_srt_q[B_*H_*L_];
__device__ int   g_srt_k[B_*H_*L_];
__device__ float g_mix_q[H_*DH_*K_];
__device__ float g_mix_k[H_*DH_*K_];
__device__ float g_psum_q[B_*H_*K_];
__device__ float g_fsum_q[B_*H_*K_];
__device__ float g_psum_k[B_*H_*K_];
__device__ float g_fsum_k[B_*H_*K_];

__device__ __nv_bfloat16 g_xhi[BL_*DM_];
__device__ __nv_bfloat16 g_xlo[BL_*DM_];
__device__ __nv_bfloat16 g_qhi[BL_*HD_];
__device__ __nv_bfloat16 g_qlo[BL_*HD_];
__device__ __nv_bfloat16 g_khi[BL_*HD_];
__device__ __nv_bfloat16 g_klo[BL_*HD_];
__device__ __nv_bfloat16 g_vhi[BL_*HD_];
__device__ __nv_bfloat16 g_vlo[BL_*HD_];
__device__ __nv_bfloat16 g_ohi[BL_*HD_];
__device__ __nv_bfloat16 g_olo[BL_*HD_];
__device__ __nv_bfloat16 g_wThi[3*DM_*HD_];
__device__ __nv_bfloat16 g_wTlo[3*DM_*HD_];
__device__ __nv_bfloat16 g_woThi[DM_*HD_];
__device__ __nv_bfloat16 g_woTlo[DM_*HD_];
__device__ float g_wsc[DM_*256];
__device__ float g_bsc[256];
__device__ float g_scores[(size_t)BL_*256];

__device__ __forceinline__ uint32_t smem_u32(const void* p) {
    uint32_t a;
    asm("{ .reg .u64 t; cvta.to.shared.u64 t, %1; cvt.u32.u64 %0, t; }" : "=r"(a) : "l"(p));
    return a;
}
__device__ __forceinline__ uint32_t pack_bf16(float a, float b) {
    __nv_bfloat162 t;
    t.x = __float2bfloat16(a); t.y = __float2bfloat16(b);
    return *(uint32_t*)&t;
}
__device__ __forceinline__ float bf_res(float a) {
    return a - __bfloat162float(__float2bfloat16(a));
}
#define MMA16816(d, a0,a1,a2,a3, b0,b1) \
    asm volatile("mma.sync.aligned.m16n8k16.row.col.f32.bf16.bf16.f32 " \
        "{%0,%1,%2,%3}, {%4,%5,%6,%7}, {%8,%9}, {%0,%1,%2,%3};" \
        : "+f"((d)[0]), "+f"((d)[1]), "+f"((d)[2]), "+f"((d)[3]) \
        : "r"(a0), "r"(a1), "r"(a2), "r"(a3), "r"(b0), "r"(b1))
#define LDSM4(R0,R1,R2,R3,ADDR) \
    asm volatile("ldmatrix.sync.aligned.m8n8.x4.shared.b16 {%0,%1,%2,%3}, [%4];" \
        : "=r"(R0), "=r"(R1), "=r"(R2), "=r"(R3) : "r"(ADDR))
#define LDSM4T(R0,R1,R2,R3,ADDR) \
    asm volatile("ldmatrix.sync.aligned.m8n8.x4.trans.shared.b16 {%0,%1,%2,%3}, [%4];" \
        : "=r"(R0), "=r"(R1), "=r"(R2), "=r"(R3) : "r"(ADDR))
#define CPA16(DST, SRC) \
    asm volatile("cp.async.cg.shared.global [%0], [%1], 16;" :: "r"(DST), "l"(SRC))

/* ===================== prep ===================== */
__global__ void prep_kernel(const float* __restrict__ wsh,
                            const float* __restrict__ wqs,
                            const float* __restrict__ wks) {
    int i = blockIdx.x * blockDim.x + threadIdx.x;
    if (i < H_*DH_*K_) {
        float s = wsh[i];
        g_mix_q[i] = 0.9f * s + 0.1f * wqs[i];
        g_mix_k[i] = 0.9f * s + 0.1f * wks[i];
    }
    if (i < B_*H_*K_) {
        g_psum_q[i] = 0.f; g_fsum_q[i] = 0.f;
        g_psum_k[i] = 0.f; g_fsum_k[i] = 0.f;
    }
}

/* pre-contract score weights */
__global__ void wsc_kernel(const float* __restrict__ wq, const float* __restrict__ wk,
                           const float* __restrict__ bq, const float* __restrict__ bk) {
    int i = blockIdx.x * 256 + threadIdx.x;
    int dm = i >> 8, col = i & 255;
    int isK = col >> 7, hc = col & 127;
    int h = hc >> 3, k = hc & 7;
    const float* w   = isK ? wk : wq;
    const float* mix = isK ? g_mix_k : g_mix_q;
    float s = 0.f;
#pragma unroll 8
    for (int d = 0; d < 64; d++)
        s += w[dm*1024 + h*64 + d] * mix[h*512 + d*8 + k];
    g_wsc[dm*256 + col] = s;
    if (i < 256) {
        const float* bb = isK ? bk : bq;
        float t = 0.f;
        for (int d = 0; d < 64; d++) t += bb[h*64 + d] * mix[h*512 + d*8 + k];
        g_bsc[col] = t;
    }
}

/* ===================== fp32 -> hi/lo bf16 split ===================== */
__global__ void split_kernel(const float* __restrict__ in,
                             __nv_bfloat16* __restrict__ hi,
                             __nv_bfloat16* __restrict__ lo, int n4) {
    int i = blockIdx.x * blockDim.x + threadIdx.x;
    if (i >= n4) return;
    float4 v = ((const float4*)in)[i];
    ((uint32_t*)hi)[i*2]   = pack_bf16(v.x, v.y);
    ((uint32_t*)hi)[i*2+1] = pack_bf16(v.z, v.w);
    ((uint32_t*)lo)[i*2]   = pack_bf16(bf_res(v.x), bf_res(v.y));
    ((uint32_t*)lo)[i*2+1] = pack_bf16(bf_res(v.z), bf_res(v.w));
}

/* transpose [1024,1024] fp32 -> [N,K] hi/lo bf16 */
__global__ void transpose_split_kernel(const float* __restrict__ in,
                                       __nv_bfloat16* __restrict__ hi,
                                       __nv_bfloat16* __restrict__ lo) {
    __shared__ float t[32][33];
    int bx = blockIdx.x * 32, by = blockIdx.y * 32;
    int x = threadIdx.x, y = threadIdx.y;
#pragma unroll
    for (int i = 0; i < 32; i += 8)
        t[y + i][x] = in[(size_t)(by + y + i) * 1024 + bx + x];
    __syncthreads();
#pragma unroll
    for (int i = 0; i < 32; i += 8) {
        float v = t[x][y + i];
        size_t oidx = (size_t)(bx + y + i) * 1024 + by + x;
        hi[oidx] = __float2bfloat16(v);
        lo[oidx] = __float2bfloat16(bf_res(v));
    }
}

/* ============ HMMA split-bf16 GEMM (R13: BK=64, 48 stages) ============ */
#define GBK 64
#define GSTR 72
#define STAGE_ELEMS (2*128*GSTR)
#define SMEM_MMA (3*STAGE_ELEMS*2)

__global__ __launch_bounds__(256, 2) void gemm_mma_kernel(
    const __nv_bfloat16* __restrict__ Ahi, const __nv_bfloat16* __restrict__ Alo,
    const __nv_bfloat16* __restrict__ WhiB, const __nv_bfloat16* __restrict__ WloB,
    const float* __restrict__ bias0, const float* __restrict__ bias1,
    const float* __restrict__ bias2,
    float* __restrict__ Cf, int obf,
    __nv_bfloat16* __restrict__ Qh, __nv_bfloat16* __restrict__ Ql,
    __nv_bfloat16* __restrict__ Kh, __nv_bfloat16* __restrict__ Kl,
    __nv_bfloat16* __restrict__ Vh, __nv_bfloat16* __restrict__ Vl) {
    extern __shared__ __align__(16) __nv_bfloat16 sm[];
    int tid = threadIdx.x, lane = tid & 31, w = tid >> 5;
    int wm = w & 1, wn = w >> 1;
    int Nbase = blockIdx.x * 128, Mbase = blockIdx.y * 128;
    int z = blockIdx.z;
    const __nv_bfloat16* Whi = WhiB + (size_t)z * DM_ * HD_;
    const __nv_bfloat16* Wlo = WloB + (size_t)z * DM_ * HD_;
    const float* bias = (z == 0) ? bias0 : (z == 1) ? bias1 : bias2;

    float acc[4][4][4];
#pragma unroll
    for (int m = 0; m < 4; m++)
#pragma unroll
        for (int n = 0; n < 4; n++)
#pragma unroll
            for (int e = 0; e < 4; e++) acc[m][n][e] = 0.f;

    int ldrow = tid >> 3, ldch = tid & 7;
    uint32_t smbase = smem_u32(sm);

    int a_off = ((wm * 64 + (lane & 15)) * GSTR + ((lane >> 4) << 3)) * 2;
    int b_off = ((wn * 32 + (lane & 7) + (((lane >> 4) & 1) << 3)) * GSTR
                 + (((lane >> 3) & 1) << 3)) * 2;

    auto load_stage = [&](int s) {
        int st = s % 3;
        int kb = s * GBK;
        int blk = kb >> 10;
        const __nv_bfloat16* As = (blk == 1) ? Alo : Ahi;
        const __nv_bfloat16* Ws = (blk == 2) ? Wlo : Whi;
        int kk = kb & (DM_ - 1);
        __nv_bfloat16* sA = sm + st * STAGE_ELEMS;
        __nv_bfloat16* sB = sA + 128 * GSTR;
#pragma unroll
        for (int i = 0; i < 4; i++) {
            int row = ldrow + i * 32;
            const __nv_bfloat16* srcA = As + (size_t)(Mbase + row) * DM_ + kk + ldch * 8;
            CPA16(smem_u32(sA + row * GSTR + ldch * 8), srcA);
            const __nv_bfloat16* srcB = Ws + (size_t)(Nbase + row) * DM_ + kk + ldch * 8;
            CPA16(smem_u32(sB + row * GSTR + ldch * 8), srcB);
        }
    };

    load_stage(0); asm volatile("cp.async.commit_group;" ::: "memory");
    load_stage(1); asm volatile("cp.async.commit_group;" ::: "memory");

    for (int s = 0; s < 48; s++) {
        int st = s % 3;
        if (s < 47) asm volatile("cp.async.wait_group 1;" ::: "memory");
        else        asm volatile("cp.async.wait_group 0;" ::: "memory");
        __syncthreads();
        uint32_t uA = smbase + st * STAGE_ELEMS * 2;
        uint32_t uB = uA + 128 * GSTR * 2;
#pragma unroll
        for (int kt = 0; kt < 4; kt++) {
            int cb = kt * 16 * 2;
            uint32_t a[4][4];
#pragma unroll
            for (int mt = 0; mt < 4; mt++)
                LDSM4(a[mt][0], a[mt][1], a[mt][2], a[mt][3],
                      uA + a_off + mt * 16 * GSTR * 2 + cb);
            uint32_t b[4][2];
#pragma unroll
            for (int p2 = 0; p2 < 2; p2++)
                LDSM4(b[p2*2][0], b[p2*2][1], b[p2*2+1][0], b[p2*2+1][1],
                      uB + b_off + p2 * 16 * GSTR * 2 + cb);
#pragma unroll
            for (int mt = 0; mt < 4; mt++)
#pragma unroll
                for (int nt = 0; nt < 4; nt++)
                    MMA16816(acc[mt][nt], a[mt][0], a[mt][1], a[mt][2], a[mt][3],
                             b[nt][0], b[nt][1]);
        }
        if (s + 2 < 48) {
            load_stage(s + 2);
            asm volatile("cp.async.commit_group;" ::: "memory");
        }
    }

    int gr0 = Mbase + wm * 64 + (lane >> 2);
    int gc0 = Nbase + wn * 32 + (lane & 3) * 2;
    if (obf) {
        __nv_bfloat16* Hi = (z == 0) ? Qh : (z == 1) ? Kh : Vh;
        __nv_bfloat16* Lo = (z == 0) ? Ql : (z == 1) ? Kl : Vl;
        float scale = (z == 0) ? 0.125f : 1.f;
#pragma unroll
        for (int mt = 0; mt < 4; mt++) {
#pragma unroll
            for (int nt = 0; nt < 4; nt++) {
                int r = gr0 + mt * 16;
                int cc = gc0 + nt * 8;
                float b0 = bias[cc], b1 = bias[cc + 1];
                float v0 = (acc[mt][nt][0] + b0) * scale;
                float v1 = (acc[mt][nt][1] + b1) * scale;
                float v2 = (acc[mt][nt][2] + b0) * scale;
                float v3 = (acc[mt][nt][3] + b1) * scale;
                *(uint32_t*)(Hi + (size_t)r * 1024 + cc) = pack_bf16(v0, v1);
                *(uint32_t*)(Lo + (size_t)r * 1024 + cc) = pack_bf16(bf_res(v0), bf_res(v1));
                *(uint32_t*)(Hi + (size_t)(r + 8) * 1024 + cc) = pack_bf16(v2, v3);
                *(uint32_t*)(Lo + (size_t)(r + 8) * 1024 + cc) = pack_bf16(bf_res(v2), bf_res(v3));
            }
        }
    } else {
#pragma unroll
        for (int mt = 0; mt < 4; mt++) {
#pragma unroll
            for (int nt = 0; nt < 4; nt++) {
                int r = gr0 + mt * 16;
                int cc = gc0 + nt * 8;
                float b0 = bias[cc], b1 = bias[cc + 1];
                float2 v0 = make_float2(acc[mt][nt][0] + b0, acc[mt][nt][1] + b1);
                float2 v1 = make_float2(acc[mt][nt][2] + b0, acc[mt][nt][3] + b1);
                *(float2*)(Cf + (size_t)r * 1024 + cc) = v0;
                *(float2*)(Cf + (size_t)(r + 8) * 1024 + cc) = v1;
            }
        }
    }
}

/* ===================== fp32 GEMM (score path) ===================== */
#define BM 128
#define BN 128
#define BK 16
__global__ __launch_bounds__(256) void gemm_bias_kernel(
    const float* __restrict__ A, const float* __restrict__ Bm,
    const float* __restrict__ bias, float* __restrict__ C,
    int M, int N, int Kd) {
    __shared__ float As[BK][BM + 4];
    __shared__ float Bs[BK][BN];
    int tid = threadIdx.x;
    int brow = blockIdx.y * BM;
    int bcol = blockIdx.x * BN;
    int tx = tid & 15, ty = tid >> 4;
    float acc[8][8];
#pragma unroll
    for (int i = 0; i < 8; i++)
#pragma unroll
        for (int j = 0; j < 8; j++) acc[i][j] = 0.f;

    for (int k0 = 0; k0 < Kd; k0 += BK) {
#pragma unroll
        for (int i = 0; i < 2; i++) {
            int lin = tid + i * 256;
            int r = lin >> 2, kc = (lin & 3) * 4;
            float4 av = *(const float4*)(A + (size_t)(brow + r) * Kd + k0 + kc);
            As[kc + 0][r] = av.x; As[kc + 1][r] = av.y;
            As[kc + 2][r] = av.z; As[kc + 3][r] = av.w;
        }
#pragma unroll
        for (int i = 0; i < 2; i++) {
            int lin = tid + i * 256;
            int r = lin >> 5, c = (lin & 31) * 4;
            *(float4*)&Bs[r][c] = *(const float4*)(Bm + (size_t)(k0 + r) * N + bcol + c);
        }
        __syncthreads();
#pragma unroll
        for (int kk = 0; kk < BK; kk++) {
            float4 a0 = *(const float4*)&As[kk][ty * 8];
            float4 a1 = *(const float4*)&As[kk][ty * 8 + 4];
            float4 b0 = *(const float4*)&Bs[kk][tx * 8];
            float4 b1 = *(const float4*)&Bs[kk][tx * 8 + 4];
            float a[8] = {a0.x,a0.y,a0.z,a0.w,a1.x,a1.y,a1.z,a1.w};
            float bb[8] = {b0.x,b0.y,b0.z,b0.w,b1.x,b1.y,b1.z,b1.w};
#pragma unroll
            for (int i = 0; i < 8; i++)
#pragma unroll
                for (int j = 0; j < 8; j++) acc[i][j] += a[i] * bb[j];
        }
        __syncthreads();
    }
#pragma unroll
    for (int i = 0; i < 8; i++) {
        int r = brow + ty * 8 + i;
#pragma unroll
        for (int j = 0; j < 8; j += 4) {
            int c = bcol + tx * 8 + j;
            float4 ov = make_float4(acc[i][j]   + bias[c],
                                    acc[i][j+1] + bias[c+1],
                                    acc[i][j+2] + bias[c+2],
                                    acc[i][j+3] + bias[c+3]);
            *(float4*)(C + (size_t)r * N + c) = ov;
        }
    }
}

/* ============ argmax + routing-loss accumulation ============ */
__global__ __launch_bounds__(256) void argmax_kernel(
    const float* __restrict__ sc, int off,
    int* __restrict__ bid, float* __restrict__ p_sum, float* __restrict__ f_sum) {
    __shared__ float red_p[16][K_];
    __shared__ float red_f[16][K_];
    int tid = threadIdx.x;
    if (tid < 128) { ((float*)red_p)[tid] = 0.f; ((float*)red_f)[tid] = 0.f; }
    __syncthreads();
    int i = blockIdx.x * 256 + tid;
    int h = i & 15, bl = i >> 4;
    int b = bl >> 12, l = bl & (L_ - 1);
    const float* s = sc + (size_t)bl * 256 + off + h * 8;
    float v[K_];
    float4 s0 = *(const float4*)s;
    float4 s1 = *(const float4*)(s + 4);
    v[0]=s0.x; v[1]=s0.y; v[2]=s0.z; v[3]=s0.w;
    v[4]=s1.x; v[5]=s1.y; v[6]=s1.z; v[7]=s1.w;
    int am = 0; float mx = v[0];
#pragma unroll
    for (int k = 1; k < K_; k++) if (v[k] > mx) { mx = v[k]; am = k; }
    bid[(b * H_ + h) * L_ + l] = am;
    float esum = 0.f, e[K_];
#pragma unroll
    for (int k = 0; k < K_; k++) { e[k] = __expf(v[k] - mx); esum += e[k]; }
    float inv = 1.f / esum;
#pragma unroll
    for (int k = 0; k < K_; k++) atomicAdd(&red_p[h][k], e[k] * inv);
    atomicAdd(&red_f[h][am], 1.f);
    __syncthreads();
    if (tid < 128) {
        int hh = tid >> 3, kk = tid & 7;
        atomicAdd(&p_sum[(b * H_ + hh) * K_ + kk], red_p[hh][kk]);
        atomicAdd(&f_sum[(b * H_ + hh) * K_ + kk], red_f[hh][kk]);
    }
}

/* ============ stable counting sort ============ */
__global__ __launch_bounds__(512) void sort_kernel(const int* __restrict__ bid,
                                                   int* __restrict__ srt) {
    __shared__ int cnt[K_][513];
    __shared__ int bstart[K_];
    int bh = blockIdx.x;
    const int* bb = bid + (size_t)bh * L_;
    int t = threadIdx.x;
    int myb[8], local[K_];
#pragma unroll
    for (int k = 0; k < K_; k++) local[k] = 0;
#pragma unroll
    for (int j = 0; j < 8; j++) { myb[j] = bb[t * 8 + j]; local[myb[j]]++; }
#pragma unroll
    for (int k = 0; k < K_; k++) cnt[k][t + 1] = local[k];
    if (t < K_) cnt[t][0] = 0;
    __syncthreads();
    if (t < K_) {
        int run = 0;
        for (int i = 1; i <= 512; i++) { run += cnt[t][i]; cnt[t][i] = run; }
    }
    __syncthreads();
    if (t == 0) {
        int a = 0;
        for (int k = 0; k < K_; k++) { bstart[k] = a; a += cnt[k][512]; }
    }
    __syncthreads();
    int off[K_];
#pragma unroll
    for (int k = 0; k < K_; k++) off[k] = bstart[k] + cnt[k][t];
    int* so = srt + (size_t)bh * L_;
#pragma unroll
    for (int j = 0; j < 8; j++) {
        int bkt = myb[j];
        so[off[bkt]++] = t * 8 + j;
    }
}

/* ============== FA2-style flash attention (proven R13 version) ======== */
#define AQHI 0
#define AQLO 9216
#define AKHI 18432
#define AKLO 27648
#define AVHI 36864
#define AVLO 46080
#define AT_SMEM 55296

__global__ __launch_bounds__(128, 3) void attn_mma_kernel() {
    extern __shared__ __align__(16) char sb[];
    uint32_t sbase = smem_u32(sb);

    int tid = threadIdx.x, lane = tid & 31, w = tid >> 5;
    int lr = lane >> 2, lq = lane & 3;
    int idx = blockIdx.x;
    int qt    = idx & 7;
    int chunk = (idx >> 3) & 7;
    int h     = (idx >> 6) & 15;
    int b     = idx >> 10;
    int qbase = (b * H_ + h) * L_ + chunk * C_ + qt * 64;
    int kbase = (b * H_ + h) * L_ + chunk * C_;

    int a_off = ((w * 16 + (lane & 15)) * 72 + ((lane >> 4) << 3)) * 2;
    int k_off = (((lane & 7) + (((lane >> 4) & 1) << 3)) * 72
                 + (((lane >> 3) & 1) << 3)) * 2;
    int v_off = (((lane & 7) + (((lane >> 3) & 1) << 3)) * 72
                 + (((lane >> 4) & 1) << 3)) * 2;

    {
        int r = tid >> 1, cc = (tid & 1) * 32;
        int qi = g_srt_q[qbase + r];
        size_t go = (size_t)(b * L_ + qi) * HD_ + h * DH_ + cc;
        int e = (r * 72 + cc) * 2;
#pragma unroll
        for (int j = 0; j < 4; j++) {
            *(uint4*)(sb + AQHI + e + j * 16) = ((const uint4*)(g_qhi + go))[j];
            *(uint4*)(sb + AQLO + e + j * 16) = ((const uint4*)(g_qlo + go))[j];
        }
    }
    __syncthreads();

    uint32_t qa[2][4][4];
#pragma unroll
    for (int kb = 0; kb < 4; kb++) {
        LDSM4(qa[0][kb][0], qa[0][kb][1], qa[0][kb][2], qa[0][kb][3],
              sbase + AQHI + a_off + kb * 32);
        LDSM4(qa[1][kb][0], qa[1][kb][1], qa[1][kb][2], qa[1][kb][3],
              sbase + AQLO + a_off + kb * 32);
    }

    int qi0 = g_srt_q[qbase + w * 16 + lr];
    int qi1 = g_srt_q[qbase + w * 16 + lr + 8];

    float acc_o[8][4];
#pragma unroll
    for (int nt = 0; nt < 8; nt++)
#pragma unroll
        for (int e = 0; e < 4; e++) acc_o[nt][e] = 0.f;
    float m0 = -1e30f, m1 = -1e30f, l0 = 0.f, l1 = 0.f;

    for (int t = 0; t < 8; t++) {
        __syncthreads();
        {
            int r = tid >> 1, cc = (tid & 1) * 32;
            int ki = g_srt_k[kbase + t * 64 + r];
            size_t go = (size_t)(b * L_ + ki) * HD_ + h * DH_ + cc;
            int e = (r * 72 + cc) * 2;
#pragma unroll
            for (int j = 0; j < 4; j++) {
                *(uint4*)(sb + AKHI + e + j * 16) = ((const uint4*)(g_khi + go))[j];
                *(uint4*)(sb + AKLO + e + j * 16) = ((const uint4*)(g_klo + go))[j];
                *(uint4*)(sb + AVHI + e + j * 16) = ((const uint4*)(g_vhi + go))[j];
                *(uint4*)(sb + AVLO + e + j * 16) = ((const uint4*)(g_vlo + go))[j];
            }
        }
        __syncthreads();

        float acc_s[8][4];
#pragma unroll
        for (int nt = 0; nt < 8; nt++)
#pragma unroll
            for (int e = 0; e < 4; e++) acc_s[nt][e] = 0.f;

#pragma unroll
        for (int kb = 0; kb < 4; kb++) {
#pragma unroll
            for (int p2 = 0; p2 < 4; p2++) {
                uint32_t bh0, bh1, bh2, bh3, bl0, bl1, bl2, bl3;
                LDSM4(bh0, bh1, bh2, bh3,
                      sbase + AKHI + k_off + p2 * 2304 + kb * 32);
                LDSM4(bl0, bl1, bl2, bl3,
                      sbase + AKLO + k_off + p2 * 2304 + kb * 32);
                MMA16816(acc_s[2*p2],   qa[0][kb][0], qa[0][kb][1], qa[0][kb][2], qa[0][kb][3], bh0, bh1);
                MMA16816(acc_s[2*p2+1], qa[0][kb][0], qa[0][kb][1], qa[0][kb][2], qa[0][kb][3], bh2, bh3);
                MMA16816(acc_s[2*p2],   qa[1][kb][0], qa[1][kb][1], qa[1][kb][2], qa[1][kb][3], bh0, bh1);
                MMA16816(acc_s[2*p2+1], qa[1][kb][0], qa[1][kb][1], qa[1][kb][2], qa[1][kb][3], bh2, bh3);
                MMA16816(acc_s[2*p2],   qa[0][kb][0], qa[0][kb][1], qa[0][kb][2], qa[0][kb][3], bl0, bl1);
                MMA16816(acc_s[2*p2+1], qa[0][kb][0], qa[0][kb][1], qa[0][kb][2], qa[0][kb][3], bl2, bl3);
            }
        }

        float mx0 = -1e30f, mx1 = -1e30f;
#pragma unroll
        for (int nt = 0; nt < 8; nt++) {
            mx0 = fmaxf(mx0, fmaxf(acc_s[nt][0], acc_s[nt][1]));
            mx1 = fmaxf(mx1, fmaxf(acc_s[nt][2], acc_s[nt][3]));
        }
        mx0 = fmaxf(mx0, __shfl_xor_sync(0xffffffff, mx0, 1));
        mx0 = fmaxf(mx0, __shfl_xor_sync(0xffffffff, mx0, 2));
        mx1 = fmaxf(mx1, __shfl_xor_sync(0xffffffff, mx1, 1));
        mx1 = fmaxf(mx1, __shfl_xor_sync(0xffffffff, mx1, 2));
        float mn0 = fmaxf(m0, mx0), mn1 = fmaxf(m1, mx1);
        float c0 = __expf(m0 - mn0), c1 = __expf(m1 - mn1);
        m0 = mn0; m1 = mn1;
        l0 *= c0; l1 *= c1;
#pragma unroll
        for (int nt = 0; nt < 8; nt++) {
            acc_o[nt][0] *= c0; acc_o[nt][1] *= c0;
            acc_o[nt][2] *= c1; acc_o[nt][3] *= c1;
        }

        float s0 = 0.f, s1 = 0.f;
#pragma unroll
        for (int nt = 0; nt < 8; nt++) {
            acc_s[nt][0] = __expf(acc_s[nt][0] - mn0);
            acc_s[nt][1] = __expf(acc_s[nt][1] - mn0);
            acc_s[nt][2] = __expf(acc_s[nt][2] - mn1);
            acc_s[nt][3] = __expf(acc_s[nt][3] - mn1);
            s0 += acc_s[nt][0] + acc_s[nt][1];
            s1 += acc_s[nt][2] + acc_s[nt][3];
        }
        s0 += __shfl_xor_sync(0xffffffff, s0, 1);
        s0 += __shfl_xor_sync(0xffffffff, s0, 2);
        s1 += __shfl_xor_sync(0xffffffff, s1, 1);
        s1 += __shfl_xor_sync(0xffffffff, s1, 2);
        l0 += s0; l1 += s1;

#pragma unroll
        for (int kb = 0; kb < 4; kb++) {
            uint32_t ph0 = pack_bf16(acc_s[2*kb][0],   acc_s[2*kb][1]);
            uint32_t ph1 = pack_bf16(acc_s[2*kb][2],   acc_s[2*kb][3]);
            uint32_t ph2 = pack_bf16(acc_s[2*kb+1][0], acc_s[2*kb+1][1]);
            uint32_t ph3 = pack_bf16(acc_s[2*kb+1][2], acc_s[2*kb+1][3]);
            uint32_t pl0 = pack_bf16(bf_res(acc_s[2*kb][0]),   bf_res(acc_s[2*kb][1]));
            uint32_t pl1 = pack_bf16(bf_res(acc_s[2*kb][2]),   bf_res(acc_s[2*kb][3]));
            uint32_t pl2 = pack_bf16(bf_res(acc_s[2*kb+1][0]), bf_res(acc_s[2*kb+1][1]));
            uint32_t pl3 = pack_bf16(bf_res(acc_s[2*kb+1][2]), bf_res(acc_s[2*kb+1][3]));
#pragma unroll
            for (int p2 = 0; p2 < 4; p2++) {
                uint32_t vh0, vh1, vh2, vh3, vl0, vl1, vl2, vl3;
                LDSM4T(vh0, vh1, vh2, vh3,
                       sbase + AVHI + v_off + kb * 2304 + p2 * 32);
                LDSM4T(vl0, vl1, vl2, vl3,
                       sbase + AVLO + v_off + kb * 2304 + p2 * 32);
                MMA16816(acc_o[2*p2],   ph0, ph1, ph2, ph3, vh0, vh1);
                MMA16816(acc_o[2*p2+1], ph0, ph1, ph2, ph3, vh2, vh3);
                MMA16816(acc_o[2*p2],   pl0, pl1, pl2, pl3, vh0, vh1);
                MMA16816(acc_o[2*p2+1], pl0, pl1, pl2, pl3, vh2, vh3);
                MMA16816(acc_o[2*p2],   ph0, ph1, ph2, ph3, vl0, vl1);
                MMA16816(acc_o[2*p2+1], ph0, ph1, ph2, ph3, vl2, vl3);
            }
        }
    }

    float inv0 = 1.f / l0, inv1 = 1.f / l1;
    size_t ro0 = (size_t)(b * L_ + qi0) * HD_ + h * DH_;
    size_t ro1 = (size_t)(b * L_ + qi1) * HD_ + h * DH_;
#pragma unroll
    for (int nt = 0; nt < 8; nt++) {
        int cc = nt * 8 + lq * 2;
        float a0 = acc_o[nt][0] * inv0, a1 = acc_o[nt][1] * inv0;
        float b0 = acc_o[nt][2] * inv1, b1 = acc_o[nt][3] * inv1;
        *(uint32_t*)(g_ohi + ro0 + cc) = pack_bf16(a0, a1);
        *(uint32_t*)(g_olo + ro0 + cc) = pack_bf16(bf_res(a0), bf_res(a1));
        *(uint32_t*)(g_ohi + ro1 + cc) = pack_bf16(b0, b1);
        *(uint32_t*)(g_olo + ro1 + cc) = pack_bf16(bf_res(b0), bf_res(b1));
    }
}

/* ============== parallel loss finalize (64 threads, 1 block) ============ */
__global__ void loss_kernel(float* __restrict__ out, int out_size) {
    if (out_size <= BL_ * DM_) return;
    int i = threadIdx.x;                  /* 64 = B_*H_ */
    const float invL = 1.f / (float)L_;
    float v = 0.f;
#pragma unroll
    for (int k = 0; k < K_; k++) {
        v += (g_fsum_q[i*K_+k] * invL) * (g_psum_q[i*K_+k] * invL);
        v += (g_fsum_k[i*K_+k] * invL) * (g_psum_k[i*K_+k] * invL);
    }
#pragma unroll
    for (int o = 16; o > 0; o >>= 1)
        v += __shfl_xor_sync(0xffffffff, v, o);
    __shared__ float sred[2];
    if ((i & 31) == 0) sred[i >> 5] = v;
    __syncthreads();
    if (i == 0)
        out[BL_ * DM_] = 0.5f * (float)K_ * (sred[0] + sred[1]) / (float)(B_ * H_);
}

/* ============ side streams / events (static init) ============ */
static cudaStream_t g_s2 = 0, g_s3 = 0;
static cudaEvent_t g_ev0 = 0, g_ev1 = 0, g_ev2 = 0;
namespace {
struct InitOnce {
    InitOnce() {
        cudaFree(0);
        cudaStreamCreateWithFlags(&g_s2, cudaStreamNonBlocking);
        cudaStreamCreateWithFlags(&g_s3, cudaStreamNonBlocking);
        cudaEventCreateWithFlags(&g_ev0, cudaEventDisableTiming);
        cudaEventCreateWithFlags(&g_ev1, cudaEventDisableTiming);
        cudaEventCreateWithFlags(&g_ev2, cudaEventDisableTiming);
    }
};
static InitOnce g_init_once;
}

/* ===================== launch ===================== */
extern "C" void kernel_launch(void* const* d_in, const int* in_sizes, int n_in,
                              void* d_out, int out_size) {
    const float* x   = (const float*)d_in[0];
    const float* wq  = (const float*)d_in[1];
    const float* bq  = (const float*)d_in[2];
    const float* wk  = (const float*)d_in[3];
    const float* bk  = (const float*)d_in[4];
    const float* wv  = (const float*)d_in[5];
    const float* bv  = (const float*)d_in[6];
    const float* wsh = (const float*)d_in[7];
    const float* wqs = (const float*)d_in[8];
    const float* wks = (const float*)d_in[9];
    const float* wo  = (const float*)d_in[10];
    const float* bo  = (const float*)d_in[11];
    float* out = (float*)d_out;

    void* p;
    cudaGetSymbolAddress(&p, g_bid_q); int* bidq = (int*)p;
    cudaGetSymbolAddress(&p, g_bid_k); int* bidk = (int*)p;
    cudaGetSymbolAddress(&p, g_srt_q); int* srtq = (int*)p;
    cudaGetSymbolAddress(&p, g_srt_k); int* srtk = (int*)p;
    cudaGetSymbolAddress(&p, g_psum_q); float* psq = (float*)p;
    cudaGetSymbolAddress(&p, g_fsum_q); float* fsq = (float*)p;
    cudaGetSymbolAddress(&p, g_psum_k); float* psk = (float*)p;
    cudaGetSymbolAddress(&p, g_fsum_k); float* fsk = (float*)p;
    cudaGetSymbolAddress(&p, g_xhi); __nv_bfloat16* xhi = (__nv_bfloat16*)p;
    cudaGetSymbolAddress(&p, g_xlo); __nv_bfloat16* xlo = (__nv_bfloat16*)p;
    cudaGetSymbolAddress(&p, g_qhi); __nv_bfloat16* qhi = (__nv_bfloat16*)p;
    cudaGetSymbolAddress(&p, g_qlo); __nv_bfloat16* qlo = (__nv_bfloat16*)p;
    cudaGetSymbolAddress(&p, g_khi); __nv_bfloat16* khi = (__nv_bfloat16*)p;
    cudaGetSymbolAddress(&p, g_klo); __nv_bfloat16* klo = (__nv_bfloat16*)p;
    cudaGetSymbolAddress(&p, g_vhi); __nv_bfloat16* vhi = (__nv_bfloat16*)p;
    cudaGetSymbolAddress(&p, g_vlo); __nv_bfloat16* vlo = (__nv_bfloat16*)p;
    cudaGetSymbolAddress(&p, g_ohi); __nv_bfloat16* ohi = (__nv_bfloat16*)p;
    cudaGetSymbolAddress(&p, g_olo); __nv_bfloat16* olo = (__nv_bfloat16*)p;
    cudaGetSymbolAddress(&p, g_wThi); __nv_bfloat16* wThi = (__nv_bfloat16*)p;
    cudaGetSymbolAddress(&p, g_wTlo); __nv_bfloat16* wTlo = (__nv_bfloat16*)p;
    cudaGetSymbolAddress(&p, g_woThi); __nv_bfloat16* woThi = (__nv_bfloat16*)p;
    cudaGetSymbolAddress(&p, g_woTlo); __nv_bfloat16* woTlo = (__nv_bfloat16*)p;
    cudaGetSymbolAddress(&p, g_wsc); float* wsc = (float*)p;
    cudaGetSymbolAddress(&p, g_bsc); float* bsc = (float*)p;
    cudaGetSymbolAddress(&p, g_scores); float* scores = (float*)p;

    cudaFuncSetAttribute(gemm_mma_kernel,
                         cudaFuncAttributeMaxDynamicSharedMemorySize, SMEM_MMA);
    cudaFuncSetAttribute(attn_mma_kernel,
                         cudaFuncAttributeMaxDynamicSharedMemorySize, AT_SMEM);

    /* ---- fork: s2 = split(x); s3 = weight transposes; join into QKV GEMM */
    cudaEventRecord(g_ev0, 0);
    cudaStreamWaitEvent(g_s2, g_ev0, 0);
    cudaStreamWaitEvent(g_s3, g_ev0, 0);

    split_kernel<<<(BL_*DM_/4 + 255)/256, 256, 0, g_s2>>>(x, xhi, xlo, BL_*DM_/4);

    dim3 tg(32, 32), tb(32, 8);
    transpose_split_kernel<<<tg, tb, 0, g_s3>>>(wq, wThi,             wTlo);
    transpose_split_kernel<<<tg, tb, 0, g_s3>>>(wk, wThi + DM_*HD_,   wTlo + DM_*HD_);
    transpose_split_kernel<<<tg, tb, 0, g_s3>>>(wv, wThi + 2*DM_*HD_, wTlo + 2*DM_*HD_);
    transpose_split_kernel<<<tg, tb, 0, g_s3>>>(wo, woThi,            woTlo);
    cudaEventRecord(g_ev2, g_s3);

    cudaStreamWaitEvent(g_s2, g_ev2, 0);
    gemm_mma_kernel<<<dim3(8, 128, 3), 256, SMEM_MMA, g_s2>>>(
        xhi, xlo, wThi, wTlo, bq, bk, bv,
        nullptr, 1, qhi, qlo, khi, klo, vhi, vlo);
    cudaEventRecord(g_ev1, g_s2);

    /* ---- main stream: score / argmax / sort path (overlapped) ---- */
    prep_kernel<<<32, 256>>>(wsh, wqs, wks);
    wsc_kernel<<<1024, 256>>>(wq, wk, bq, bk);
    gemm_bias_kernel<<<dim3(2, 128), 256>>>(x, wsc, bsc, scores, BL_, 256, DM_);
    argmax_kernel<<<1024, 256>>>(scores, 0,   bidq, psq, fsq);
    argmax_kernel<<<1024, 256>>>(scores, 128, bidk, psk, fsk);
    sort_kernel<<<B_*H_, 512>>>(bidq, srtq);
    sort_kernel<<<B_*H_, 512>>>(bidk, srtk);

    /* ---- join, then attention + output projection + parallel loss ---- */
    cudaStreamWaitEvent(0, g_ev1, 0);
    attn_mma_kernel<<<4096, 128, AT_SMEM>>>();
    gemm_mma_kernel<<<dim3(8, 128, 1), 256, SMEM_MMA>>>(
        ohi, olo, woThi, woTlo, bo, bo, bo,
        out, 0, nullptr, nullptr, nullptr, nullptr, nullptr, nullptr);
    loss_kernel<<<1, 64>>>(out, out_size);
}